// round 3
// baseline (speedup 1.0000x reference)
#include <cuda_runtime.h>
#include <math.h>

#define C 100            // number of classes (static in reference)
#define D 256            // feature dim
#define SLICE 64         // dims per warp in pass 1 (float2 per lane)
#define NSLICES (D / SLICE)     // 4
#define ACC_WARPS 2      // warps per accumulate block; smem = 2*100*64*4 = 51.2KB
#define GY 148           // 4*148 = 592 blocks = one full wave at 4 blocks/SM
#define BATCH 16         // rows per pipelined register batch (per warp)

__device__ float g_sums[C * D];
__device__ float g_counts[C];
__device__ int   g_label_is_i64;   // 1 => labels are int64 (stride-2 int32 words)

// ---------------------------------------------------------------------------
// Kernel 0: zero scratch, init flag, and detect label dtype in one launch.
// If labels are little-endian int64 (<2^31) every odd 32-bit word is zero;
// if int32, odd words hold labels (uniform 0..99) and are nonzero somewhere.
// Note: flag starts at 1; only 0-writes race with reads? No reads here —
// ordering vs. later kernels is by launch boundary.
// ---------------------------------------------------------------------------
__global__ void k_init(const unsigned int* __restrict__ lw, int nwords) {
    int i = blockIdx.x * blockDim.x + threadIdx.x;
    if (i == 0) g_label_is_i64 = 1;
    if (i < C * D) g_sums[i] = 0.0f;
    if (i < C)     g_counts[i] = 0.0f;
    int idx = 2 * i + 1;
    if (idx < nwords && lw[idx] != 0u) g_label_is_i64 = 0;
}
// flag write race: the i==0 store and any 0-store are in the same kernel.
// Fix: dedicate a second tiny kernel ordering? Simpler: set the flag via
// k_init only when i==0 AND nothing else writes 1. A store of 1 racing a
// store of 0 is undefined order. Use a separate seed kernel instead:
__global__ void k_seed() { g_label_is_i64 = 1; }
__global__ void k_detect(const unsigned int* __restrict__ lw, int nwords) {
    int i = blockIdx.x * blockDim.x + threadIdx.x;
    if (i < C * D) g_sums[i] = 0.0f;
    if (i < C)     g_counts[i] = 0.0f;
    int idx = 2 * i + 1;
    if (idx < nwords && lw[idx] != 0u) g_label_is_i64 = 0;
}

__device__ __forceinline__ int load_label(const int* __restrict__ l32, int i, int is64) {
    return __ldg(&l32[is64 ? (i << 1) : i]);
}

// ---------------------------------------------------------------------------
// Kernel 1: segment-sum of feat into g_sums (+ fused label histogram on the
// slice-0 blocks). Grid: (NSLICES, GY). Block: 64 threads = 2 warps.
// Each warp owns a private smem accumulator acc[warp][C][SLICE]; lane l
// handles dims slice*64 + 2l, 2l+1 via float2 — LDS.64/STS.64 conflict-free.
// Double-buffered register batches keep 16 x 256B = 4KB in flight per warp.
// ---------------------------------------------------------------------------
__global__ void __launch_bounds__(ACC_WARPS * 32)
k_accum(const float2* __restrict__ feat2, const int* __restrict__ l32,
        int N, int rows_per_block) {
    __shared__ float acc[ACC_WARPS][C][SLICE];
    __shared__ int   hist[C];

    const int w    = threadIdx.x >> 5;
    const int lane = threadIdx.x & 31;
    // this thread's float2 column within the row (row = 128 float2)
    const int dcol2 = blockIdx.x * (SLICE / 2) + lane;

    for (int i = threadIdx.x; i < ACC_WARPS * C * SLICE; i += blockDim.x)
        ((float*)acc)[i] = 0.0f;
    if (blockIdx.x == 0)
        for (int i = threadIdx.x; i < C; i += blockDim.x) hist[i] = 0;
    __syncthreads();

    const int is64 = g_label_is_i64;
    const int r0 = blockIdx.y * rows_per_block;
    const int r1 = min(r0 + rows_per_block, N);

    float2* __restrict__ accv = (float2*)&acc[w][0][0];   // [C*32] float2
    const int step = ACC_WARPS;
    const int first = r0 + w;
    const int cnt = (r1 > first) ? (r1 - first + step - 1) / step : 0;
    const int nb  = cnt / BATCH;

    float2 vA[BATCH], vB[BATCH];
    int    lA[BATCH], lB[BATCH];

#define LOADB(V, L, RBASE)                                                    \
    {                                                                         \
        const int _rb = (RBASE);                                              \
        _Pragma("unroll")                                                     \
        for (int j = 0; j < BATCH; j++) {                                     \
            const int rr = _rb + j * step;                                    \
            (L)[j] = load_label(l32, rr, is64);                               \
            (V)[j] = __ldg(&feat2[(size_t)rr * (D / 2) + dcol2]);             \
        }                                                                     \
    }

#define RMWB(V, L)                                                            \
    {                                                                         \
        _Pragma("unroll")                                                     \
        for (int j = 0; j < BATCH; j++) {                                     \
            const int a = (L)[j] * (SLICE / 2) + lane;                        \
            float2 t = accv[a];                                               \
            t.x += (V)[j].x; t.y += (V)[j].y;                                 \
            accv[a] = t;                                                      \
        }                                                                     \
    }

    if (nb > 0) {
        LOADB(vA, lA, first);
        int b = 1;
        for (; b + 1 < nb; b += 2) {
            LOADB(vB, lB, first + b * BATCH * step);
            RMWB(vA, lA);
            LOADB(vA, lA, first + (b + 1) * BATCH * step);
            RMWB(vB, lB);
        }
        if (b < nb) {
            LOADB(vB, lB, first + b * BATCH * step);
            RMWB(vA, lA);
            RMWB(vB, lB);
        } else {
            RMWB(vA, lA);
        }
    }
    for (int rr = first + nb * BATCH * step; rr < r1; rr += step) {
        const int la = load_label(l32, rr, is64);
        const float2 v = __ldg(&feat2[(size_t)rr * (D / 2) + dcol2]);
        const int a = la * (SLICE / 2) + lane;
        float2 t = accv[a];
        t.x += v.x; t.y += v.y;
        accv[a] = t;
    }

#undef LOADB
#undef RMWB

    if (blockIdx.x == 0) {
        for (int i = r0 + threadIdx.x; i < r1; i += blockDim.x)
            atomicAdd(&hist[load_label(l32, i, is64)], 1);
    }
    __syncthreads();

    // reduce warp copies, flush with atomics (148 contenders per address)
    const int dbase = blockIdx.x * SLICE;
    for (int i = threadIdx.x; i < C * SLICE; i += blockDim.x) {
        float s = 0.0f;
        #pragma unroll
        for (int ww = 0; ww < ACC_WARPS; ww++) s += (&acc[ww][0][0])[i];
        const int cls = i / SLICE;
        const int dd  = i - cls * SLICE;
        atomicAdd(&g_sums[cls * D + dbase + dd], s);
    }
    if (blockIdx.x == 0) {
        for (int i = threadIdx.x; i < C; i += blockDim.x)
            if (hist[i]) atomicAdd(&g_counts[i], (float)hist[i]);
    }
}

// ---------------------------------------------------------------------------
// Kernel 2: per-row distance to own-class center, with the center computed
// on the fly as sums[lab]*inv_cnt (kills the finalize kernel; sums+counts
// are L2-resident). One warp per row; lane reads 2x float4 of feat and sums.
// ---------------------------------------------------------------------------
__global__ void __launch_bounds__(256)
k_dist(const float* __restrict__ feat, const int* __restrict__ l32,
       float* __restrict__ out, int N) {
    const int warp = (int)((blockIdx.x * blockDim.x + threadIdx.x) >> 5);
    const int lane = threadIdx.x & 31;
    if (warp >= N) return;

    const int is64 = g_label_is_i64;
    const int lab = load_label(l32, warp, is64);

    const float cnt = __ldg(&g_counts[lab]);
    const float inv = (cnt > 0.0f) ? (1.0f / cnt) : 0.0f;

    const float4* __restrict__ f4 = (const float4*)(feat + (size_t)warp * D);
    const float4* __restrict__ s4 = (const float4*)(g_sums + (size_t)lab * D);

    const float4 fa = __ldcs(&f4[lane]);        // streaming: don't pollute L2
    const float4 fb = __ldcs(&f4[lane + 32]);
    const float4 sa = __ldg(&s4[lane]);
    const float4 sb = __ldg(&s4[lane + 32]);

    float s = 0.0f, dx;
    dx = fa.x - sa.x * inv; s = fmaf(dx, dx, s);
    dx = fa.y - sa.y * inv; s = fmaf(dx, dx, s);
    dx = fa.z - sa.z * inv; s = fmaf(dx, dx, s);
    dx = fa.w - sa.w * inv; s = fmaf(dx, dx, s);
    dx = fb.x - sb.x * inv; s = fmaf(dx, dx, s);
    dx = fb.y - sb.y * inv; s = fmaf(dx, dx, s);
    dx = fb.z - sb.z * inv; s = fmaf(dx, dx, s);
    dx = fb.w - sb.w * inv; s = fmaf(dx, dx, s);

    #pragma unroll
    for (int o = 16; o; o >>= 1) s += __shfl_xor_sync(0xffffffffu, s, o);

    if (lane == 0) out[warp] = sqrtf(s);
}

// ---------------------------------------------------------------------------
extern "C" void kernel_launch(void* const* d_in, const int* in_sizes, int n_in,
                              void* d_out, int out_size) {
    const float* feat = (const float*)d_in[0];
    const int*   l32  = (const int*)d_in[1];   // int32 view; stride decided on device
    float* out = (float*)d_out;

    const int N = in_sizes[0] / D;             // 500000

    k_seed<<<1, 32>>>();
    {
        int work = (N / 2 > C * D) ? N / 2 : C * D;
        k_detect<<<(work + 255) / 256, 256>>>((const unsigned int*)l32, N);
    }
    {
        int rpb = (N + GY - 1) / GY;
        dim3 grid(NSLICES, GY);
        k_accum<<<grid, ACC_WARPS * 32>>>((const float2*)feat, l32, N, rpb);
    }
    {
        int rows_per_block = 256 / 32;         // 8 warps -> 8 rows per block
        int blocks = (N + rows_per_block - 1) / rows_per_block;
        k_dist<<<blocks, 256>>>(feat, l32, out, N);
    }
}

// round 4
// speedup vs baseline: 1.0426x; 1.0426x over previous
#include <cuda_runtime.h>
#include <math.h>

#define C 100            // number of classes (static in reference)
#define D 256            // feature dim
#define SLICE 64         // dims per warp in pass 1 (float2 per lane)
#define NSLICES (D / SLICE)     // 4
#define ACC_WARPS 2      // warps per accumulate block; smem = 2*100*64*4 = 51.2KB
#define GY 148           // 4*148 = 592 blocks = one full wave at 4 blocks/SM
#define BATCH 16         // rows per pipelined register batch (per warp)

__device__ float g_sums[C * D];
__device__ float g_counts[C];
__device__ int   g_label_is_i64;   // 1 => labels are int64 (stride-2 int32 words)

// ---------------------------------------------------------------------------
// Seed the dtype flag (separate launch: no write-race with detection zeroes)
// ---------------------------------------------------------------------------
__global__ void k_seed() { g_label_is_i64 = 1; }

// ---------------------------------------------------------------------------
// Zero scratch + detect label dtype. If labels are little-endian int64
// (<2^31) every odd 32-bit word is zero; if int32, odd words hold labels
// (uniform 0..99) and are nonzero somewhere among 250K samples.
// ---------------------------------------------------------------------------
__global__ void k_detect(const unsigned int* __restrict__ lw, int nwords) {
    int i = blockIdx.x * blockDim.x + threadIdx.x;
    if (i < C * D) g_sums[i] = 0.0f;
    if (i < C)     g_counts[i] = 0.0f;
    int idx = 2 * i + 1;
    if (idx < nwords && lw[idx] != 0u) g_label_is_i64 = 0;
}

__device__ __forceinline__ int load_label(const int* __restrict__ l32, int i, int is64) {
    return __ldg(&l32[is64 ? (i << 1) : i]);
}

// ---------------------------------------------------------------------------
// Kernel 1: segment-sum of feat into g_sums (+ fused histogram on slice 0).
// Grid (NSLICES, GY), block 64 = 2 warps, each warp a private smem
// accumulator acc[warp][C][SLICE]; lane owns 2 dims via float2 (conflict-free
// LDS.64/STS.64). Depth-3 software pipeline: up to 2 full register batches
// (2 x 4KB/warp) outstanding -> 64KB in flight per SM at 8 warps/SM.
// ---------------------------------------------------------------------------
__global__ void __launch_bounds__(ACC_WARPS * 32)
k_accum(const float2* __restrict__ feat2, const int* __restrict__ l32,
        int N, int rows_per_block) {
    __shared__ float acc[ACC_WARPS][C][SLICE];
    __shared__ int   hist[C];

    const int w    = threadIdx.x >> 5;
    const int lane = threadIdx.x & 31;
    const int dcol2 = blockIdx.x * (SLICE / 2) + lane;  // float2 column in row

    for (int i = threadIdx.x; i < ACC_WARPS * C * SLICE; i += blockDim.x)
        ((float*)acc)[i] = 0.0f;
    if (blockIdx.x == 0)
        for (int i = threadIdx.x; i < C; i += blockDim.x) hist[i] = 0;
    __syncthreads();

    const int is64 = g_label_is_i64;
    const int r0 = blockIdx.y * rows_per_block;
    const int r1 = min(r0 + rows_per_block, N);

    float2* __restrict__ accv = (float2*)&acc[w][0][0];   // [C*32] float2
    const int step = ACC_WARPS;
    const int first = r0 + w;
    const int cnt = (r1 > first) ? (r1 - first + step - 1) / step : 0;
    const int nb  = cnt / BATCH;
    const int bstride = BATCH * step;

    float2 vA[BATCH], vB[BATCH], vC[BATCH];
    int    lA[BATCH], lB[BATCH], lC[BATCH];

#define LOADB(V, L, BI)                                                       \
    {                                                                         \
        const int _rb = first + (BI) * bstride;                               \
        _Pragma("unroll")                                                     \
        for (int j = 0; j < BATCH; j++) {                                     \
            const int rr = _rb + j * step;                                    \
            (L)[j] = load_label(l32, rr, is64);                               \
            (V)[j] = __ldg(&feat2[(size_t)rr * (D / 2) + dcol2]);             \
        }                                                                     \
    }

#define RMWB(V, L)                                                            \
    {                                                                         \
        _Pragma("unroll")                                                     \
        for (int j = 0; j < BATCH; j++) {                                     \
            const int a = (L)[j] * (SLICE / 2) + lane;                        \
            float2 t = accv[a];                                               \
            t.x += (V)[j].x; t.y += (V)[j].y;                                 \
            accv[a] = t;                                                      \
        }                                                                     \
    }

    if (nb >= 2) {
        LOADB(vA, lA, 0);
        LOADB(vB, lB, 1);
        int b = 0;
        // steady state: 3 batches per iteration, RMW trails loads by 2 stages
        for (; b + 5 <= nb; b += 3) {
            LOADB(vC, lC, b + 2); RMWB(vA, lA);
            LOADB(vA, lA, b + 3); RMWB(vB, lB);
            LOADB(vB, lB, b + 4); RMWB(vC, lC);
        }
        const int rem = nb - b;            // 2, 3, or 4
        if (rem == 2) {
            RMWB(vA, lA); RMWB(vB, lB);
        } else if (rem == 3) {
            LOADB(vC, lC, b + 2); RMWB(vA, lA);
            RMWB(vB, lB); RMWB(vC, lC);
        } else {                            // rem == 4
            LOADB(vC, lC, b + 2); RMWB(vA, lA);
            LOADB(vA, lA, b + 3); RMWB(vB, lB);
            RMWB(vC, lC); RMWB(vA, lA);
        }
    } else if (nb == 1) {
        LOADB(vA, lA, 0);
        RMWB(vA, lA);
    }
    // tail rows
    for (int rr = first + nb * bstride; rr < r1; rr += step) {
        const int la = load_label(l32, rr, is64);
        const float2 v = __ldg(&feat2[(size_t)rr * (D / 2) + dcol2]);
        const int a = la * (SLICE / 2) + lane;
        float2 t = accv[a];
        t.x += v.x; t.y += v.y;
        accv[a] = t;
    }

#undef LOADB
#undef RMWB

    if (blockIdx.x == 0) {
        for (int i = r0 + threadIdx.x; i < r1; i += blockDim.x)
            atomicAdd(&hist[load_label(l32, i, is64)], 1);
    }
    __syncthreads();

    // reduce warp copies, flush with atomics (148 contenders per address)
    const int dbase = blockIdx.x * SLICE;
    for (int i = threadIdx.x; i < C * SLICE; i += blockDim.x) {
        float s = 0.0f;
        #pragma unroll
        for (int ww = 0; ww < ACC_WARPS; ww++) s += (&acc[ww][0][0])[i];
        const int cls = i / SLICE;
        const int dd  = i - cls * SLICE;
        atomicAdd(&g_sums[cls * D + dbase + dd], s);
    }
    if (blockIdx.x == 0) {
        for (int i = threadIdx.x; i < C; i += blockDim.x)
            if (hist[i]) atomicAdd(&g_counts[i], (float)hist[i]);
    }
}

// ---------------------------------------------------------------------------
// Kernel 2: per-row distance to own-class center (= sums*inv_cnt on the fly).
// TWO rows per warp; all 8 global loads issued before any compute so each
// warp keeps 512B of feat in flight (2x R3) -> ~24KB/SM feat MLP.
// ---------------------------------------------------------------------------
__global__ void __launch_bounds__(256)
k_dist(const float* __restrict__ feat, const int* __restrict__ l32,
       float* __restrict__ out, int N) {
    const int gw   = (int)((blockIdx.x * blockDim.x + threadIdx.x) >> 5);
    const int lane = threadIdx.x & 31;
    const int row0 = 2 * gw;
    const int row1 = row0 + 1;
    if (row0 >= N) return;
    const bool has1 = (row1 < N);

    const int is64 = g_label_is_i64;
    const int lab0 = load_label(l32, row0, is64);
    const int lab1 = has1 ? load_label(l32, row1, is64) : lab0;

    const float4* __restrict__ f0 = (const float4*)(feat + (size_t)row0 * D);
    const float4* __restrict__ f1 = (const float4*)(feat + (size_t)row1 * D);
    const float4* __restrict__ s0 = (const float4*)(g_sums + (size_t)lab0 * D);
    const float4* __restrict__ s1 = (const float4*)(g_sums + (size_t)lab1 * D);

    // issue all loads up front
    const float4 fa0 = __ldcs(&f0[lane]);
    const float4 fb0 = __ldcs(&f0[lane + 32]);
    const float4 fa1 = has1 ? __ldcs(&f1[lane])      : make_float4(0,0,0,0);
    const float4 fb1 = has1 ? __ldcs(&f1[lane + 32]) : make_float4(0,0,0,0);
    const float4 sa0 = __ldg(&s0[lane]);
    const float4 sb0 = __ldg(&s0[lane + 32]);
    const float4 sa1 = __ldg(&s1[lane]);
    const float4 sb1 = __ldg(&s1[lane + 32]);

    const float c0 = __ldg(&g_counts[lab0]);
    const float c1 = __ldg(&g_counts[lab1]);
    const float inv0 = (c0 > 0.0f) ? (1.0f / c0) : 0.0f;
    const float inv1 = (c1 > 0.0f) ? (1.0f / c1) : 0.0f;

    float d0 = 0.0f, d1 = 0.0f, dx;
    dx = fa0.x - sa0.x * inv0; d0 = fmaf(dx, dx, d0);
    dx = fa0.y - sa0.y * inv0; d0 = fmaf(dx, dx, d0);
    dx = fa0.z - sa0.z * inv0; d0 = fmaf(dx, dx, d0);
    dx = fa0.w - sa0.w * inv0; d0 = fmaf(dx, dx, d0);
    dx = fb0.x - sb0.x * inv0; d0 = fmaf(dx, dx, d0);
    dx = fb0.y - sb0.y * inv0; d0 = fmaf(dx, dx, d0);
    dx = fb0.z - sb0.z * inv0; d0 = fmaf(dx, dx, d0);
    dx = fb0.w - sb0.w * inv0; d0 = fmaf(dx, dx, d0);

    dx = fa1.x - sa1.x * inv1; d1 = fmaf(dx, dx, d1);
    dx = fa1.y - sa1.y * inv1; d1 = fmaf(dx, dx, d1);
    dx = fa1.z - sa1.z * inv1; d1 = fmaf(dx, dx, d1);
    dx = fa1.w - sa1.w * inv1; d1 = fmaf(dx, dx, d1);
    dx = fb1.x - sb1.x * inv1; d1 = fmaf(dx, dx, d1);
    dx = fb1.y - sb1.y * inv1; d1 = fmaf(dx, dx, d1);
    dx = fb1.z - sb1.z * inv1; d1 = fmaf(dx, dx, d1);
    dx = fb1.w - sb1.w * inv1; d1 = fmaf(dx, dx, d1);

    #pragma unroll
    for (int o = 16; o; o >>= 1) {
        d0 += __shfl_xor_sync(0xffffffffu, d0, o);
        d1 += __shfl_xor_sync(0xffffffffu, d1, o);
    }

    if (lane == 0) {
        out[row0] = sqrtf(d0);
        if (has1) out[row1] = sqrtf(d1);
    }
}

// ---------------------------------------------------------------------------
extern "C" void kernel_launch(void* const* d_in, const int* in_sizes, int n_in,
                              void* d_out, int out_size) {
    const float* feat = (const float*)d_in[0];
    const int*   l32  = (const int*)d_in[1];   // int32 view; stride decided on device
    float* out = (float*)d_out;

    const int N = in_sizes[0] / D;             // 500000

    k_seed<<<1, 32>>>();
    {
        int work = (N / 2 > C * D) ? N / 2 : C * D;
        k_detect<<<(work + 255) / 256, 256>>>((const unsigned int*)l32, N);
    }
    {
        int rpb = (N + GY - 1) / GY;
        dim3 grid(NSLICES, GY);
        k_accum<<<grid, ACC_WARPS * 32>>>((const float2*)feat, l32, N, rpb);
    }
    {
        // 8 warps/block, 2 rows per warp -> 16 rows per block
        int blocks = (N + 15) / 16;
        k_dist<<<blocks, 256>>>(feat, l32, out, N);
    }
}